// round 13
// baseline (speedup 1.0000x reference)
#include <cuda_runtime.h>
#include <math.h>

#define D_     196
#define NCH_   64
#define H_     8
#define DH_    64
#define INNER_ 512
#define MLP_   784
#define SEQ_   65
#define NG_QKV 384   // 1536/4
#define NG_D   49    // 196/4
#define NG_MLP 196   // 784/4
#define GRID_  98
#define NT_    512

// ---- scratch (__device__ globals; no allocations allowed) ----
__device__ float  g_a[NCH_ * D_];
__device__ float4 g_xatt4[SEQ_ * NG_D];
__device__ float4 g_qkv4[SEQ_ * NG_QKV];    // q(pre-scaled)|k|v
__device__ float4 g_o4[SEQ_ * 128];         // attention output [row][512f]
__device__ float4 g_x2_4[SEQ_ * NG_D];      // after attn residuals
__device__ float4 g_t4[SEQ_ * NG_MLP];      // gelu(ff1) [row][784f]
__device__ unsigned g_cnt;                  // barrier arrival counter (self-resetting)
__device__ unsigned g_gen;                  // barrier generation (monotonic)

__device__ __forceinline__ void fma4(float4& a, float h, const float4& w) {
    a.x += h * w.x; a.y += h * w.y; a.z += h * w.z; a.w += h * w.w;
}
__device__ __forceinline__ void add4(float4& a, const float4& b) {
    a.x += b.x; a.y += b.y; a.z += b.z; a.w += b.w;
}
__device__ __forceinline__ float gelu_exact(float v) {
    return 0.5f * v * (1.f + erff(v * 0.70710678118654752f));
}

// grid-wide barrier: gridDim.x (98) <= #SMs (148), 1 block/SM -> co-resident, no deadlock.
__device__ __forceinline__ void gsync() {
    __syncthreads();
    if (threadIdx.x == 0) {
        unsigned gen = *(volatile unsigned*)&g_gen;
        __threadfence();
        if (atomicAdd(&g_cnt, 1u) == gridDim.x - 1u) {
            atomicExch(&g_cnt, 0u);
            __threadfence();
            atomicAdd(&g_gen, 1u);
        } else {
            while (*(volatile unsigned*)&g_gen == gen) { __nanosleep(32); }
        }
        __threadfence();
    }
    __syncthreads();
}

__global__ __launch_bounds__(NT_, 1) void k_fused(
    const float* __restrict__ x, const float* __restrict__ tokens,
    const float* __restrict__ x_pe, const float* __restrict__ conv_k,
    const float* __restrict__ bn_g, const float* __restrict__ bn_b,
    const float* __restrict__ bn_rm, const float* __restrict__ bn_rv,
    const float* __restrict__ fc_w1, const float* __restrict__ fc_w2,
    const float* __restrict__ ln1_g, const float* __restrict__ ln1_b,
    const float4* __restrict__ wqkv4,
    const float4* __restrict__ wout4, const float4* __restrict__ bout4,
    const float* __restrict__ ln2_g, const float* __restrict__ ln2_b,
    const float4* __restrict__ ffw1_4, const float4* __restrict__ ffb1_4,
    const float4* __restrict__ ffw2_4, const float4* __restrict__ ffb2_4,
    float4* __restrict__ out4)
{
    __shared__ __align__(16) float smf[9216];   // 36 KB static, reused per phase
    const int tid = threadIdx.x;
    const int b   = blockIdx.x;

    // ========== P1: on-the-fly LN1 + QKV (96 blocks x 4 f4-cols) + gating (96) ==========
    if (b < 96) {
        float*  g1s = smf;                 // 196
        float*  b1s = smf + 196;           // 196
        float*  mr  = smf + 392;           // 65
        float*  rr  = smf + 460;           // 65
        float4* red = (float4*)(smf + 528);// 260 f4 (cl*65+row)

        if (tid < D_) { g1s[tid] = ln1_g[tid]; b1s[tid] = ln1_b[tid]; }
        {
            int w = tid >> 5, lane = tid & 31;
            for (int row = w; row < SEQ_; row += 16) {
                const float* xr = x + row * D_;
                float s1 = 0.f, s2 = 0.f;
                #pragma unroll
                for (int i2 = 0; i2 < 7; i2++) {
                    int k = lane + 32 * i2;
                    if (k < D_) { float v = xr[k]; s1 += v; s2 += v * v; }
                }
                #pragma unroll
                for (int o = 16; o; o >>= 1) {
                    s1 += __shfl_down_sync(0xffffffffu, s1, o);
                    s2 += __shfl_down_sync(0xffffffffu, s2, o);
                }
                if (lane == 0) {
                    float m = s1 * (1.f / 196.f);
                    float var = s2 * (1.f / 196.f) - m * m;
                    mr[row] = m; rr[row] = rsqrtf(var + 1e-5f);
                }
            }
        }
        __syncthreads();

        // items: (cl 0..3) x (row 0..64) x (ks 0..1) = 520
        int cl0, row0, ks0;
        float4 a0 = make_float4(0.f, 0.f, 0.f, 0.f);
        {
            int i = tid;
            cl0 = i / 130; int rem = i - cl0 * 130; row0 = rem >> 1; ks0 = rem & 1;
            int kb = ks0 * 98;
            float m = mr[row0], rv = rr[row0];
            const float* xr = x + row0 * D_ + kb;
            const float* g1 = g1s + kb;
            const float* bb = b1s + kb;
            const float4* W = wqkv4 + kb * NG_QKV + 4 * b + cl0;
            #pragma unroll 7
            for (int k = 0; k < 98; k++) {
                float h = (xr[k] - m) * rv * g1[k] + bb[k];
                fma4(a0, h, W[k * NG_QKV]);
            }
        }
        int cl1 = 0, row1 = 0, ks1 = 0;
        float4 a1 = make_float4(0.f, 0.f, 0.f, 0.f);
        if (tid < 8) {
            int i = 512 + tid;
            cl1 = i / 130; int rem = i - cl1 * 130; row1 = rem >> 1; ks1 = rem & 1;
            int kb = ks1 * 98;
            float m = mr[row1], rv = rr[row1];
            const float* xr = x + row1 * D_ + kb;
            const float* g1 = g1s + kb;
            const float* bb = b1s + kb;
            const float4* W = wqkv4 + kb * NG_QKV + 4 * b + cl1;
            #pragma unroll 7
            for (int k = 0; k < 98; k++) {
                float h = (xr[k] - m) * rv * g1[k] + bb[k];
                fma4(a1, h, W[k * NG_QKV]);
            }
        }
        if (ks0 == 1) red[cl0 * 65 + row0] = a0;
        if (tid < 8 && ks1 == 1) red[cl1 * 65 + row1] = a1;
        __syncthreads();
        if (ks0 == 0) {
            add4(a0, red[cl0 * 65 + row0]);
            int g = 4 * b + cl0;
            float sc = (g < 128) ? 0.125f : 1.f;
            a0.x *= sc; a0.y *= sc; a0.z *= sc; a0.w *= sc;
            g_qkv4[row0 * NG_QKV + g] = a0;
        }
        if (tid < 8 && ks1 == 0) {
            add4(a1, red[cl1 * 65 + row1]);
            int g = 4 * b + cl1;
            float sc = (g < 128) ? 0.125f : 1.f;
            a1.x *= sc; a1.y *= sc; a1.z *= sc; a1.w *= sc;
            g_qkv4[row1 * NG_QKV + g] = a1;
        }
    } else if (b == 96) {
        // ---------------- gating ----------------
        float* b1s = smf;            // 64
        float* b2s = smf + 64;       // 64
        float* hid = smf + 128;      // 12
        float* cs  = smf + 140;      // 64

        const int warp = tid >> 5, lane = tid & 31;
        const float k0 = conv_k[3], k1 = conv_k[4], k2 = conv_k[5];
        const float rm  = bn_rm[0];
        const float inv = rsqrtf(bn_rv[0] + 1e-5f) * bn_g[0];
        const float bb  = bn_b[0];

        for (int ch = warp; ch < NCH_; ch += 16) {
            const float* row = x_pe + ch * D_;
            float s = 0.f;
            for (int d = lane; d < D_; d += 32) {
                float xm = (d > 0)      ? row[d - 1] : 0.f;
                float xc = row[d];
                float xp = (d < D_ - 1) ? row[d + 1] : 0.f;
                float conv = k0 * xm + k1 * xc + k2 * xp;
                float bn = (conv - rm) * inv + bb;
                float av = fmaxf(bn, 0.f);
                g_a[ch * D_ + d] = av;
                s += av;
            }
            #pragma unroll
            for (int o = 16; o; o >>= 1) s += __shfl_down_sync(0xffffffffu, s, o);
            if (lane == 0) b1s[ch] = s * (1.f / 196.f);
        }
        __syncthreads();
        if (tid < NCH_) {
            const float bi = b1s[tid];
            float mx = -1e30f, mn = 1e30f;
            int cnt_nonpos = 0, rank = 0;
            #pragma unroll 8
            for (int j = 0; j < NCH_; j++) {
                float bj = b1s[j];
                mx = fmaxf(mx, bj); mn = fminf(mn, bj);
                if (bj <= 0.f) cnt_nonpos++;
                if (bj < bi || (bj == bi && j < tid)) rank++;
            }
            int middle = (mx < 0.f || mn > 0.f) ? 32 : (mx > 0.f ? cnt_nonpos : 0);
            float b2;
            if (rank < middle) {
                float ls = (float)middle;
                b2 = bi - 1.f / (1.f + powf(ls, bi));
            } else {
                float le = (float)(NCH_ - middle);
                b2 = bi + 1.f / (1.f + powf(le, -bi));
            }
            b2s[tid] = b2;
        }
        __syncthreads();
        if (tid < 12) {
            float s = 0.f;
            #pragma unroll 8
            for (int i = 0; i < NCH_; i++) s += b2s[i] * fc_w1[i * 12 + tid];
            hid[tid] = fmaxf(s, 0.f);
        }
        __syncthreads();
        if (tid < NCH_) {
            float s = 0.f;
            #pragma unroll
            for (int j = 0; j < 12; j++) s += hid[j] * fc_w2[j * NCH_ + tid];
            cs[tid] = 1.f / (1.f + expf(-s));
        }
        __syncthreads();
        float* xatt = (float*)g_xatt4;
        for (int idx = tid; idx < NCH_ * D_; idx += NT_)
            xatt[idx] = g_a[idx] * cs[idx / D_];
        for (int d = tid; d < D_; d += NT_)
            xatt[NCH_ * D_ + d] = tokens[d];
    }
    gsync();

    // ========== P2: attention (88 blocks = 8 heads x 11 rowgroups of 6) ==========
    if (b < 88) {
        const int h = b / 11, rg = b % 11;
        float* Ks   = smf;                 // 65*64
        float* Vs   = smf + 4160;          // 65*64
        float* qs   = smf + 8320;          // 6*64
        float* sc   = smf + 8704;          // 6*66
        float* sinv = smf + 9100;          // 6

        for (int i = tid; i < SEQ_ * 16; i += NT_) {
            int m = i >> 4, j = i & 15;
            ((float4*)Ks)[i] = g_qkv4[m * NG_QKV + 128 + h * 16 + j];
            ((float4*)Vs)[i] = g_qkv4[m * NG_QKV + 256 + h * 16 + j];
        }
        if (tid < 96) {
            int r = tid >> 4, j = tid & 15;
            int row = rg * 6 + r;
            ((float4*)qs)[tid] = (row < SEQ_) ? g_qkv4[row * NG_QKV + h * 16 + j]
                                              : make_float4(0.f, 0.f, 0.f, 0.f);
        }
        __syncthreads();
        if (tid < 390) {
            int r = tid / 65, m = tid - r * 65;
            const float4* qp = (const float4*)(qs + r * 64);
            const float4* kp = (const float4*)(Ks + m * 64);
            float s = 0.f;
            #pragma unroll
            for (int i = 0; i < 16; i++) {
                float4 q4 = qp[i], k4 = kp[i];
                s += q4.x * k4.x + q4.y * k4.y + q4.z * k4.z + q4.w * k4.w;
            }
            sc[r * 66 + m] = s;
        }
        __syncthreads();
        {
            int w = tid >> 5, lane = tid & 31;
            if (w < 6) {
                float e0 = sc[w * 66 + lane], e1 = sc[w * 66 + lane + 32];
                float e2 = (lane == 0) ? sc[w * 66 + 64] : -1e30f;
                float mx = fmaxf(fmaxf(e0, e1), e2);
                #pragma unroll
                for (int o = 16; o; o >>= 1) mx = fmaxf(mx, __shfl_down_sync(0xffffffffu, mx, o));
                mx = __shfl_sync(0xffffffffu, mx, 0);
                float x0 = expf(e0 - mx), x1 = expf(e1 - mx);
                float x2v = (lane == 0) ? expf(sc[w * 66 + 64] - mx) : 0.f;
                sc[w * 66 + lane] = x0; sc[w * 66 + lane + 32] = x1;
                if (lane == 0) sc[w * 66 + 64] = x2v;
                float s = x0 + x1 + x2v;
                #pragma unroll
                for (int o = 16; o; o >>= 1) s += __shfl_down_sync(0xffffffffu, s, o);
                if (lane == 0) sinv[w] = 1.f / s;
            }
        }
        __syncthreads();
        if (tid < 384) {
            int r = tid >> 6, d = tid & 63;
            const float* p = sc + r * 66;
            float a = 0.f;
            #pragma unroll 5
            for (int m = 0; m < SEQ_; m++) a += p[m] * Vs[m * 64 + d];
            int row = rg * 6 + r;
            if (row < SEQ_) ((float*)g_o4)[row * INNER_ + h * 64 + d] = a * sinv[r];
        }
    }
    gsync();

    // ========== P3: out-proj + residuals (2 rowhalves x 49 f4-cols) ==========
    {
        const int rh = b / 49, gcol = b - rh * 49;
        const int r0 = rh * 33;
        const int nrows = rh ? 32 : 33;
        const int items = nrows * 16;
        float4* red3 = (float4*)smf;        // up to 528 f4

        if (tid < items) {
            int r = tid >> 4, sub = tid & 15;
            const float4* op = g_o4 + (r0 + r) * 128 + sub * 8;
            const float4* wp = wout4 + sub * 32 * NG_D + gcol;
            float4 a = make_float4(0.f, 0.f, 0.f, 0.f);
            #pragma unroll
            for (int k4 = 0; k4 < 8; k4++) {
                float4 o4 = op[k4];
                fma4(a, o4.x, wp[(4 * k4 + 0) * NG_D]);
                fma4(a, o4.y, wp[(4 * k4 + 1) * NG_D]);
                fma4(a, o4.z, wp[(4 * k4 + 2) * NG_D]);
                fma4(a, o4.w, wp[(4 * k4 + 3) * NG_D]);
            }
            red3[tid] = a;
        }
        int extra = items - 512;
        if (extra > 0 && tid < extra) {
            int i = 512 + tid;
            int r = i >> 4, sub = i & 15;
            const float4* op = g_o4 + (r0 + r) * 128 + sub * 8;
            const float4* wp = wout4 + sub * 32 * NG_D + gcol;
            float4 a = make_float4(0.f, 0.f, 0.f, 0.f);
            #pragma unroll
            for (int k4 = 0; k4 < 8; k4++) {
                float4 o4 = op[k4];
                fma4(a, o4.x, wp[(4 * k4 + 0) * NG_D]);
                fma4(a, o4.y, wp[(4 * k4 + 1) * NG_D]);
                fma4(a, o4.z, wp[(4 * k4 + 2) * NG_D]);
                fma4(a, o4.w, wp[(4 * k4 + 3) * NG_D]);
            }
            red3[i] = a;
        }
        __syncthreads();
        if (tid < nrows) {
            float4 a = make_float4(0.f, 0.f, 0.f, 0.f);
            #pragma unroll
            for (int s = 0; s < 16; s++) add4(a, red3[tid * 16 + s]);
            int row = r0 + tid;
            float4 bo = bout4[gcol];
            float4 xv = ((const float4*)x)[row * NG_D + gcol];
            float4 xa = g_xatt4[row * NG_D + gcol];
            a.x += bo.x + xv.x + xa.x;
            a.y += bo.y + xv.y + xa.y;
            a.z += bo.z + xv.z + xa.z;
            a.w += bo.w + xv.w + xa.w;
            g_x2_4[row * NG_D + gcol] = a;
        }
    }
    gsync();

    // ========== P4: on-the-fly LN2 + FF1 + GELU (98 blocks x 2 f4-cols) ==========
    {
        float*  g2s = smf;                 // 196
        float*  b2s = smf + 196;           // 196
        float*  mr  = smf + 392;           // 65
        float*  rr  = smf + 460;           // 65
        float4* red = (float4*)(smf + 528);// 390 f4: (ks-1)*130 + row*2 + cl

        if (tid < D_) { g2s[tid] = ln2_g[tid]; b2s[tid] = ln2_b[tid]; }
        {
            int w = tid >> 5, lane = tid & 31;
            const float* x2f = (const float*)g_x2_4;
            for (int row = w; row < SEQ_; row += 16) {
                const float* xr = x2f + row * D_;
                float s1 = 0.f, s2 = 0.f;
                #pragma unroll
                for (int i2 = 0; i2 < 7; i2++) {
                    int k = lane + 32 * i2;
                    if (k < D_) { float v = xr[k]; s1 += v; s2 += v * v; }
                }
                #pragma unroll
                for (int o = 16; o; o >>= 1) {
                    s1 += __shfl_down_sync(0xffffffffu, s1, o);
                    s2 += __shfl_down_sync(0xffffffffu, s2, o);
                }
                if (lane == 0) {
                    float m = s1 * (1.f / 196.f);
                    float var = s2 * (1.f / 196.f) - m * m;
                    mr[row] = m; rr[row] = rsqrtf(var + 1e-5f);
                }
            }
        }
        __syncthreads();

        // items: (cl 0..1) x (row 0..64) x (ks 0..3) = 520
        int cl0, row0, ks0;
        float4 a0 = make_float4(0.f, 0.f, 0.f, 0.f);
        {
            int i = tid;
            cl0 = i & 1; int rest = i >> 1; row0 = rest >> 2; ks0 = rest & 3;
            int kb = ks0 * 49;
            float m = mr[row0], rv = rr[row0];
            const float* xr = (const float*)g_x2_4 + row0 * D_ + kb;
            const float* g2 = g2s + kb;
            const float* bb = b2s + kb;
            const float4* W = ffw1_4 + kb * NG_MLP + 2 * b + cl0;
            #pragma unroll 7
            for (int k = 0; k < 49; k++) {
                float h = (xr[k] - m) * rv * g2[k] + bb[k];
                fma4(a0, h, W[k * NG_MLP]);
            }
        }
        int cl1 = 0, row1 = 0, ks1 = 0;
        float4 a1 = make_float4(0.f, 0.f, 0.f, 0.f);
        if (tid < 8) {
            int i = 512 + tid;
            cl1 = i & 1; int rest = i >> 1; row1 = rest >> 2; ks1 = rest & 3;
            int kb = ks1 * 49;
            float m = mr[row1], rv = rr[row1];
            const float* xr = (const float*)g_x2_4 + row1 * D_ + kb;
            const float* g2 = g2s + kb;
            const float* bb = b2s + kb;
            const float4* W = ffw1_4 + kb * NG_MLP + 2 * b + cl1;
            #pragma unroll 7
            for (int k = 0; k < 49; k++) {
                float h = (xr[k] - m) * rv * g2[k] + bb[k];
                fma4(a1, h, W[k * NG_MLP]);
            }
        }
        if (ks0 > 0) red[(ks0 - 1) * 130 + row0 * 2 + cl0] = a0;
        if (tid < 8 && ks1 > 0) red[(ks1 - 1) * 130 + row1 * 2 + cl1] = a1;
        __syncthreads();
        if (ks0 == 0) {
            #pragma unroll
            for (int s = 0; s < 3; s++) add4(a0, red[s * 130 + row0 * 2 + cl0]);
            int g = 2 * b + cl0;
            float4 fb = ffb1_4[g], t;
            t.x = gelu_exact(a0.x + fb.x); t.y = gelu_exact(a0.y + fb.y);
            t.z = gelu_exact(a0.z + fb.z); t.w = gelu_exact(a0.w + fb.w);
            g_t4[row0 * NG_MLP + g] = t;
        }
        if (tid < 8 && ks1 == 0) {
            #pragma unroll
            for (int s = 0; s < 3; s++) add4(a1, red[s * 130 + row1 * 2 + cl1]);
            int g = 2 * b + cl1;
            float4 fb = ffb1_4[g], t;
            t.x = gelu_exact(a1.x + fb.x); t.y = gelu_exact(a1.y + fb.y);
            t.z = gelu_exact(a1.z + fb.z); t.w = gelu_exact(a1.w + fb.w);
            g_t4[row1 * NG_MLP + g] = t;
        }
    }
    gsync();

    // ========== P5: FF2 + residual -> out (2 rowhalves x 49 f4-cols) ==========
    {
        const int rh = b / 49, gcol = b - rh * 49;
        const int r0 = rh * 33;
        const int nrows = rh ? 32 : 33;
        const int items = nrows * 16;
        float4* red3 = (float4*)smf;

        if (tid < items) {
            int r = tid >> 4, sub = tid & 15;
            const float* tp = (const float*)g_t4 + (r0 + r) * MLP_ + sub * 49;
            const float4* wp = ffw2_4 + sub * 49 * NG_D + gcol;
            float4 a = make_float4(0.f, 0.f, 0.f, 0.f);
            #pragma unroll 7
            for (int k = 0; k < 49; k++) fma4(a, tp[k], wp[k * NG_D]);
            red3[tid] = a;
        }
        int extra = items - 512;
        if (extra > 0 && tid < extra) {
            int i = 512 + tid;
            int r = i >> 4, sub = i & 15;
            const float* tp = (const float*)g_t4 + (r0 + r) * MLP_ + sub * 49;
            const float4* wp = ffw2_4 + sub * 49 * NG_D + gcol;
            float4 a = make_float4(0.f, 0.f, 0.f, 0.f);
            #pragma unroll 7
            for (int k = 0; k < 49; k++) fma4(a, tp[k], wp[k * NG_D]);
            red3[i] = a;
        }
        __syncthreads();
        if (tid < nrows) {
            float4 a = make_float4(0.f, 0.f, 0.f, 0.f);
            #pragma unroll
            for (int s = 0; s < 16; s++) add4(a, red3[tid * 16 + s]);
            int row = r0 + tid;
            float4 fb = ffb2_4[gcol];
            float4 x2 = g_x2_4[row * NG_D + gcol];
            a.x += fb.x + x2.x; a.y += fb.y + x2.y;
            a.z += fb.z + x2.z; a.w += fb.w + x2.w;
            out4[row * NG_D + gcol] = a;
        }
    }
}

// ============================================================
extern "C" void kernel_launch(void* const* d_in, const int* in_sizes, int n_in,
                              void* d_out, int out_size)
{
    const float* x      = (const float*)d_in[0];
    const float* tokens = (const float*)d_in[1];
    const float* x_pe   = (const float*)d_in[2];
    const float* conv_k = (const float*)d_in[3];
    const float* bn_g   = (const float*)d_in[4];
    const float* bn_b   = (const float*)d_in[5];
    const float* bn_rm  = (const float*)d_in[6];
    const float* bn_rv  = (const float*)d_in[7];
    const float* fc_w1  = (const float*)d_in[8];
    const float* fc_w2  = (const float*)d_in[9];
    const float* ln1_g  = (const float*)d_in[10];
    const float* ln1_b  = (const float*)d_in[11];
    const float* ln2_g  = (const float*)d_in[12];
    const float* ln2_b  = (const float*)d_in[13];
    const float* w_qkv  = (const float*)d_in[14];
    const float* w_out  = (const float*)d_in[15];
    const float* b_out  = (const float*)d_in[16];
    const float* ff_w1  = (const float*)d_in[17];
    const float* ff_b1  = (const float*)d_in[18];
    const float* ff_w2  = (const float*)d_in[19];
    const float* ff_b2  = (const float*)d_in[20];

    k_fused<<<GRID_, NT_>>>(x, tokens, x_pe, conv_k, bn_g, bn_b, bn_rm, bn_rv,
                            fc_w1, fc_w2, ln1_g, ln1_b,
                            (const float4*)w_qkv,
                            (const float4*)w_out, (const float4*)b_out,
                            ln2_g, ln2_b,
                            (const float4*)ff_w1, (const float4*)ff_b1,
                            (const float4*)ff_w2, (const float4*)ff_b2,
                            (float4*)d_out);
}

// round 14
// speedup vs baseline: 1.6877x; 1.6877x over previous
#include <cuda_runtime.h>
#include <cuda_fp16.h>
#include <math.h>

#define D_     196
#define NCH_   64
#define H_     8
#define DH_    64
#define INNER_ 512
#define MLP_   784
#define SEQ_   65
#define NG_QKV 384   // 1536/4
#define NG_D   49    // 196/4
#define NG_MLP 196   // 784/4
#define GRID_  100
#define NT_    512

// ---- scratch (__device__ globals; no allocations allowed) ----
__device__ float  g_a[NCH_ * D_];
__device__ float4 g_xatt4[SEQ_ * NG_D];
__device__ float4 g_qkv4[SEQ_ * NG_QKV];    // q(pre-scaled)|k|v
__device__ __half g_wout_h[INNER_ * D_];    // fp16 cache of w_out
__device__ __half g_ffw1_h[D_ * MLP_];      // fp16 cache of ff_w1
__device__ __half g_ffw2_h[MLP_ * D_];      // fp16 cache of ff_w2
__device__ unsigned g_cnt;                  // barrier arrival counter (self-resetting)
__device__ unsigned g_gen;                  // barrier generation (monotonic)

__device__ __forceinline__ void fma4(float4& a, float h, const float4& w) {
    a.x += h * w.x; a.y += h * w.y; a.z += h * w.z; a.w += h * w.w;
}
__device__ __forceinline__ void add4(float4& a, const float4& b) {
    a.x += b.x; a.y += b.y; a.z += b.z; a.w += b.w;
}
__device__ __forceinline__ float gelu_exact(float v) {
    return 0.5f * v * (1.f + erff(v * 0.70710678118654752f));
}
// unpack 4 halves (8B) -> float4
__device__ __forceinline__ float4 h4tof4(uint2 u) {
    __half2 a = *reinterpret_cast<__half2*>(&u.x);
    __half2 b = *reinterpret_cast<__half2*>(&u.y);
    float2 fa = __half22float2(a), fb = __half22float2(b);
    return make_float4(fa.x, fa.y, fb.x, fb.y);
}

// grid-wide barrier: gridDim.x (100) <= #SMs (148), 1 block/SM -> all co-resident.
__device__ __forceinline__ void gsync() {
    __syncthreads();
    if (threadIdx.x == 0) {
        unsigned gen = *(volatile unsigned*)&g_gen;
        __threadfence();
        if (atomicAdd(&g_cnt, 1u) == gridDim.x - 1u) {
            atomicExch(&g_cnt, 0u);
            __threadfence();
            atomicAdd(&g_gen, 1u);
        } else {
            while (*(volatile unsigned*)&g_gen == gen) { __nanosleep(32); }
        }
        __threadfence();
    }
    __syncthreads();
}

__global__ __launch_bounds__(NT_, 1) void k_fused(
    const float* __restrict__ x, const float* __restrict__ tokens,
    const float* __restrict__ x_pe, const float* __restrict__ conv_k,
    const float* __restrict__ bn_g, const float* __restrict__ bn_b,
    const float* __restrict__ bn_rm, const float* __restrict__ bn_rv,
    const float* __restrict__ fc_w1, const float* __restrict__ fc_w2,
    const float* __restrict__ ln1_g, const float* __restrict__ ln1_b,
    const float4* __restrict__ wqkv4,
    const float4* __restrict__ wout4, const float4* __restrict__ bout4,
    const float4* __restrict__ ln2g4, const float4* __restrict__ ln2b4,
    const float4* __restrict__ ffw1_4, const float4* __restrict__ ffb1_4,
    const float4* __restrict__ ffw2_4, const float4* __restrict__ ffb2_4,
    float4* __restrict__ out4)
{
    __shared__ __align__(16) char sm[20160];
    const int tid = threadIdx.x;
    const int b   = blockIdx.x;

    // ===== P0 (no barrier needed before phase A): convert phase-B weights to fp16 =====
    {
        const int N4_WOUT = (INNER_ * D_) / 4;     // 25088
        const int N4_FFW1 = (D_ * MLP_) / 4;       // 38416
        const int N4_FFW2 = (MLP_ * D_) / 4;       // 38416
        const int gstr = GRID_ * NT_;
        int gt = b * NT_ + tid;
        for (int i = gt; i < N4_WOUT; i += gstr) {
            float4 v = wout4[i];
            uint2 u;
            *reinterpret_cast<__half2*>(&u.x) = __floats2half2_rn(v.x, v.y);
            *reinterpret_cast<__half2*>(&u.y) = __floats2half2_rn(v.z, v.w);
            reinterpret_cast<uint2*>(g_wout_h)[i] = u;
        }
        for (int i = gt; i < N4_FFW1; i += gstr) {
            float4 v = ffw1_4[i];
            uint2 u;
            *reinterpret_cast<__half2*>(&u.x) = __floats2half2_rn(v.x, v.y);
            *reinterpret_cast<__half2*>(&u.y) = __floats2half2_rn(v.z, v.w);
            reinterpret_cast<uint2*>(g_ffw1_h)[i] = u;
        }
        for (int i = gt; i < N4_FFW2; i += gstr) {
            float4 v = ffw2_4[i];
            uint2 u;
            *reinterpret_cast<__half2*>(&u.x) = __floats2half2_rn(v.x, v.y);
            *reinterpret_cast<__half2*>(&u.y) = __floats2half2_rn(v.z, v.w);
            reinterpret_cast<uint2*>(g_ffw2_h)[i] = u;
        }
    }

    // ================= PHASE A: LN1 + QKV (blocks 0..98) + gating (99) =================
    if (b < 99) {
        float*  hs   = (float*)sm;                 // 2*196 floats (ends 1568)
        float4* red  = (float4*)(sm + 1600);       // 3 slices * 128 gl * 2 rows (12288 B)
        float*  mrow = (float*)(sm + 13888);       // 2
        float*  rrow = (float*)(sm + 13896);       // 2

        const int tile  = b / 3;
        const int chunk = b - tile * 3;
        const int base  = tile * 2;                // rows base, base+1

        if (tid < 2 * D_) {
            int r = tid / D_, c = tid - r * D_;
            int row = base + r;
            hs[tid] = (row < SEQ_) ? x[row * D_ + c] : 0.f;
        }
        __syncthreads();

        const int warp = tid >> 5, lane = tid & 31;
        if (warp < 2) {
            float s1 = 0.f, s2 = 0.f;
            #pragma unroll
            for (int i = 0; i < 7; i++) {
                int c = lane + 32 * i;
                if (c < D_) { float v = hs[warp * D_ + c]; s1 += v; s2 += v * v; }
            }
            #pragma unroll
            for (int o = 16; o; o >>= 1) {
                s1 += __shfl_down_sync(0xffffffffu, s1, o);
                s2 += __shfl_down_sync(0xffffffffu, s2, o);
            }
            if (lane == 0) {
                float mean = s1 * (1.f / 196.f);
                float var  = s2 * (1.f / 196.f) - mean * mean;
                mrow[warp] = mean; rrow[warp] = rsqrtf(var + 1e-5f);
            }
        }
        __syncthreads();
        if (tid < 2 * D_) {
            int r = tid / D_, c = tid - r * D_;
            hs[tid] = (hs[tid] - mrow[r]) * rrow[r] * ln1_g[c] + ln1_b[c];
        }
        __syncthreads();

        const int gl = tid & 127;
        const int g  = chunk * 128 + gl;     // < 384
        const int s  = tid >> 7;             // K-slice 0..3, each 49
        float4 a0 = make_float4(0.f, 0.f, 0.f, 0.f);
        float4 a1 = make_float4(0.f, 0.f, 0.f, 0.f);

        const int kb = s * 49;
        const float4* W = wqkv4 + kb * NG_QKV + g;
        #pragma unroll 7
        for (int k = 0; k < 49; k++) {
            float4 w = W[k * NG_QKV];
            fma4(a0, hs[kb + k], w);
            fma4(a1, hs[D_ + kb + k], w);
        }
        if (s > 0) {
            red[((s - 1) * 128 + gl) * 2 + 0] = a0;
            red[((s - 1) * 128 + gl) * 2 + 1] = a1;
        }
        __syncthreads();
        if (s == 0) {
            float sc = (g < 128) ? 0.125f : 1.f;   // q pre-scale DH^-0.5
            #pragma unroll
            for (int ss = 0; ss < 3; ss++) {
                add4(a0, red[(ss * 128 + gl) * 2 + 0]);
                add4(a1, red[(ss * 128 + gl) * 2 + 1]);
            }
            a0.x *= sc; a0.y *= sc; a0.z *= sc; a0.w *= sc;
            a1.x *= sc; a1.y *= sc; a1.z *= sc; a1.w *= sc;
            if (base < SEQ_)     g_qkv4[base * NG_QKV + g]       = a0;
            if (base + 1 < SEQ_) g_qkv4[(base + 1) * NG_QKV + g] = a1;
        }
    } else {
        // ---------------- gating (block 99) ----------------
        float* b1s = (float*)sm;              // 64
        float* b2s = (float*)(sm + 256);      // 64
        float* hid = (float*)(sm + 512);      // 12
        float* cs  = (float*)(sm + 576);      // 64

        const int warp = tid >> 5, lane = tid & 31;
        const float k0 = conv_k[3], k1 = conv_k[4], k2 = conv_k[5];
        const float rm  = bn_rm[0];
        const float inv = rsqrtf(bn_rv[0] + 1e-5f) * bn_g[0];
        const float bb  = bn_b[0];

        for (int ch = warp; ch < NCH_; ch += 16) {
            const float* row = x_pe + ch * D_;
            float s = 0.f;
            for (int d = lane; d < D_; d += 32) {
                float xm = (d > 0)      ? row[d - 1] : 0.f;
                float xc = row[d];
                float xp = (d < D_ - 1) ? row[d + 1] : 0.f;
                float conv = k0 * xm + k1 * xc + k2 * xp;
                float bn = (conv - rm) * inv + bb;
                float av = fmaxf(bn, 0.f);
                g_a[ch * D_ + d] = av;
                s += av;
            }
            #pragma unroll
            for (int o = 16; o; o >>= 1) s += __shfl_down_sync(0xffffffffu, s, o);
            if (lane == 0) b1s[ch] = s * (1.f / 196.f);
        }
        __syncthreads();

        if (tid < NCH_) {
            const float bi = b1s[tid];
            float mx = -1e30f, mn = 1e30f;
            int cnt_nonpos = 0, rank = 0;
            #pragma unroll 8
            for (int j = 0; j < NCH_; j++) {
                float bj = b1s[j];
                mx = fmaxf(mx, bj); mn = fminf(mn, bj);
                if (bj <= 0.f) cnt_nonpos++;
                if (bj < bi || (bj == bi && j < tid)) rank++;
            }
            int middle = (mx < 0.f || mn > 0.f) ? 32 : (mx > 0.f ? cnt_nonpos : 0);
            float b2;
            if (rank < middle) {
                float ls = (float)middle;
                b2 = bi - 1.f / (1.f + powf(ls, bi));
            } else {
                float le = (float)(NCH_ - middle);
                b2 = bi + 1.f / (1.f + powf(le, -bi));
            }
            b2s[tid] = b2;
        }
        __syncthreads();
        if (tid < 12) {
            float s = 0.f;
            #pragma unroll 8
            for (int i = 0; i < NCH_; i++) s += b2s[i] * fc_w1[i * 12 + tid];
            hid[tid] = fmaxf(s, 0.f);
        }
        __syncthreads();
        if (tid < NCH_) {
            float s = 0.f;
            #pragma unroll
            for (int j = 0; j < 12; j++) s += hid[j] * fc_w2[j * NCH_ + tid];
            cs[tid] = 1.f / (1.f + expf(-s));
        }
        __syncthreads();
        float* xatt = (float*)g_xatt4;
        for (int idx = tid; idx < NCH_ * D_; idx += NT_)
            xatt[idx] = g_a[idx] * cs[idx / D_];
        for (int d = tid; d < D_; d += NT_)
            xatt[NCH_ * D_ + d] = tokens[d];
    }
    gsync();   // the ONLY grid barrier

    // ================= PHASE B: per-row pipeline (blocks 0..64) =================
    if (b >= SEQ_) return;
    const int n = b;
    const float* qkv = (const float*)g_qkv4;

    float*  qs    = (float*)sm;                // 512 f          [0,2048)
    float*  scs   = (float*)(sm + 2048);       // 8*66 f         [2048,4160)
    float*  smaxp = (float*)(sm + 4160);       // 8
    float*  sinvp = (float*)(sm + 4192);       // 8
    float*  os    = (float*)(sm + 4224);       // 512 f          [4224,6272)
    float4* red   = (float4*)(sm + 6272);      // 7*49 f4        [6272,11760)
    float4* x2s   = (float4*)(sm + 11760);     // 49 f4          [11760,12544)
    float4* h2s   = (float4*)(sm + 12544);     // 49 f4          [12544,13328)
    float*  p1    = (float*)(sm + 13328);      // 49
    float*  p2    = (float*)(sm + 13524);      // 49
    float*  stats = (float*)(sm + 13720);      // 2
    float4* ts4   = (float4*)(sm + 13744);     // 196 f4         [13744,16880)
    float4* red1  = (float4*)(sm + 16880);     // 196 f4         [16880,20016)

    // ---- attention: head h = tid>>6, lane-within-head d = tid&63 ----
    const int h = tid >> 6, d = tid & 63;
    qs[tid] = qkv[n * 1536 + tid];            // q row (pre-scaled)
    __syncthreads();

    const float* qh = qs + h * DH_;
    {
        const float4* kr = (const float4*)(qkv + d * 1536 + INNER_ + h * DH_);
        float s = 0.f;
        #pragma unroll
        for (int i = 0; i < 16; i++) {
            float4 k4 = kr[i];
            s += qh[4*i] * k4.x + qh[4*i+1] * k4.y + qh[4*i+2] * k4.z + qh[4*i+3] * k4.w;
        }
        scs[h * 66 + d] = s;
        if (d == 0) {
            const float4* kr2 = (const float4*)(qkv + 64 * 1536 + INNER_ + h * DH_);
            float s2 = 0.f;
            #pragma unroll
            for (int i = 0; i < 16; i++) {
                float4 k4 = kr2[i];
                s2 += qh[4*i] * k4.x + qh[4*i+1] * k4.y + qh[4*i+2] * k4.z + qh[4*i+3] * k4.w;
            }
            scs[h * 66 + 64] = s2;
        }
    }
    __syncthreads();
    if (d < 32) {
        float m = fmaxf(scs[h * 66 + d], scs[h * 66 + d + 32]);
        if (d == 0) m = fmaxf(m, scs[h * 66 + 64]);
        #pragma unroll
        for (int o = 16; o; o >>= 1) m = fmaxf(m, __shfl_down_sync(0xffffffffu, m, o));
        if (d == 0) smaxp[h] = m;
    }
    __syncthreads();
    {
        float mx = smaxp[h];
        scs[h * 66 + d] = expf(scs[h * 66 + d] - mx);
        if (d == 0) scs[h * 66 + 64] = expf(scs[h * 66 + 64] - mx);
    }
    __syncthreads();
    if (d < 32) {
        float s = scs[h * 66 + d] + scs[h * 66 + d + 32];
        if (d == 0) s += scs[h * 66 + 64];
        #pragma unroll
        for (int o = 16; o; o >>= 1) s += __shfl_down_sync(0xffffffffu, s, o);
        if (d == 0) sinvp[h] = 1.f / s;
    }
    __syncthreads();
    {
        const float* vb = qkv + 2 * INNER_ + h * DH_ + d;
        const float* p  = scs + h * 66;
        float acc = 0.f;
        #pragma unroll 8
        for (int m = 0; m < SEQ_; m++) acc += p[m] * vb[m * 1536];
        os[tid] = acc * sinvp[h];
    }
    __syncthreads();

    // ---- out-proj (K=512, 8 slices of 64, fp16 weights) + residuals + LN2 ----
    const int s8 = tid / NG_D;                 // 0..10 (use <8)
    const int g  = tid - s8 * NG_D;            // <49
    float4 vacc = make_float4(0.f, 0.f, 0.f, 0.f);
    if (s8 < 8) {
        const int kb = s8 * 64;
        const uint2* W = (const uint2*)g_wout_h + kb * NG_D + g;
        const float* hb = os + kb;
        #pragma unroll 8
        for (int k = 0; k < 64; k++) fma4(vacc, hb[k], h4tof4(W[k * NG_D]));
        if (s8 > 0) red[(s8 - 1) * NG_D + g] = vacc;
    }
    __syncthreads();
    if (s8 == 0) {
        #pragma unroll
        for (int ss = 0; ss < 7; ss++) add4(vacc, red[ss * NG_D + g]);
        float4 bo = bout4[g];
        float4 xv = ((const float4*)x)[n * NG_D + g];
        float4 xa = g_xatt4[n * NG_D + g];
        vacc.x += bo.x + xv.x + xa.x;
        vacc.y += bo.y + xv.y + xa.y;
        vacc.z += bo.z + xv.z + xa.z;
        vacc.w += bo.w + xv.w + xa.w;
        x2s[g] = vacc;
        p1[g] = vacc.x + vacc.y + vacc.z + vacc.w;
        p2[g] = vacc.x*vacc.x + vacc.y*vacc.y + vacc.z*vacc.z + vacc.w*vacc.w;
    }
    __syncthreads();
    if (tid < 32) {
        float t1 = 0.f, t2 = 0.f;
        for (int i = tid; i < NG_D; i += 32) { t1 += p1[i]; t2 += p2[i]; }
        #pragma unroll
        for (int o = 16; o; o >>= 1) {
            t1 += __shfl_down_sync(0xffffffffu, t1, o);
            t2 += __shfl_down_sync(0xffffffffu, t2, o);
        }
        if (tid == 0) {
            float mean = t1 * (1.f / 196.f);
            float var  = t2 * (1.f / 196.f) - mean * mean;
            stats[0] = mean; stats[1] = rsqrtf(var + 1e-5f);
        }
    }
    __syncthreads();
    if (s8 == 0) {
        float m = stats[0], rs = stats[1];
        float4 v = x2s[g], gg = ln2g4[g], bb = ln2b4[g], hh;
        hh.x = (v.x - m) * rs * gg.x + bb.x;
        hh.y = (v.y - m) * rs * gg.y + bb.y;
        hh.z = (v.z - m) * rs * gg.z + bb.z;
        hh.w = (v.w - m) * rs * gg.w + bb.w;
        h2s[g] = hh;
    }
    __syncthreads();

    // ---- FF1 (K=196, 2 slices of 98, fp16 weights) + GELU ----
    float4 facc = make_float4(0.f, 0.f, 0.f, 0.f);
    if (tid < 392) {
        const int s1 = tid / NG_MLP;           // 0..1
        const int gg = tid - s1 * NG_MLP;      // <196
        const float* hh = (const float*)h2s;   // 196 floats
        const int kb = s1 * 98;
        const uint2* W = (const uint2*)g_ffw1_h + kb * NG_MLP + gg;
        #pragma unroll 7
        for (int k = 0; k < 98; k++) fma4(facc, hh[kb + k], h4tof4(W[k * NG_MLP]));
        if (s1 == 1) red1[gg] = facc;
    }
    __syncthreads();
    if (tid < NG_MLP) {
        add4(facc, red1[tid]);
        float4 fb = ffb1_4[tid], t;
        t.x = gelu_exact(facc.x + fb.x);
        t.y = gelu_exact(facc.y + fb.y);
        t.z = gelu_exact(facc.z + fb.z);
        t.w = gelu_exact(facc.w + fb.w);
        ts4[tid] = t;
    }
    __syncthreads();

    // ---- FF2 (K=784, 8 slices of 98, fp16 weights) + residual -> out ----
    float4 oacc = make_float4(0.f, 0.f, 0.f, 0.f);
    if (s8 < 8) {
        const int kb = s8 * 98;
        const float* tf = (const float*)ts4;   // 784 floats
        const uint2* W = (const uint2*)g_ffw2_h + kb * NG_D + g;
        #pragma unroll 7
        for (int k = 0; k < 98; k++) fma4(oacc, tf[kb + k], h4tof4(W[k * NG_D]));
        if (s8 > 0) red[(s8 - 1) * NG_D + g] = oacc;
    }
    __syncthreads();
    if (s8 == 0) {
        #pragma unroll
        for (int ss = 0; ss < 7; ss++) add4(oacc, red[ss * NG_D + g]);
        float4 fb = ffb2_4[g], x2 = x2s[g];
        oacc.x += fb.x + x2.x; oacc.y += fb.y + x2.y;
        oacc.z += fb.z + x2.z; oacc.w += fb.w + x2.w;
        out4[n * NG_D + g] = oacc;
    }
}

// ============================================================
extern "C" void kernel_launch(void* const* d_in, const int* in_sizes, int n_in,
                              void* d_out, int out_size)
{
    const float* x      = (const float*)d_in[0];
    const float* tokens = (const float*)d_in[1];
    const float* x_pe   = (const float*)d_in[2];
    const float* conv_k = (const float*)d_in[3];
    const float* bn_g   = (const float*)d_in[4];
    const float* bn_b   = (const float*)d_in[5];
    const float* bn_rm  = (const float*)d_in[6];
    const float* bn_rv  = (const float*)d_in[7];
    const float* fc_w1  = (const float*)d_in[8];
    const float* fc_w2  = (const float*)d_in[9];
    const float* ln1_g  = (const float*)d_in[10];
    const float* ln1_b  = (const float*)d_in[11];
    const float* ln2_g  = (const float*)d_in[12];
    const float* ln2_b  = (const float*)d_in[13];
    const float* w_qkv  = (const float*)d_in[14];
    const float* w_out  = (const float*)d_in[15];
    const float* b_out  = (const float*)d_in[16];
    const float* ff_w1  = (const float*)d_in[17];
    const float* ff_b1  = (const float*)d_in[18];
    const float* ff_w2  = (const float*)d_in[19];
    const float* ff_b2  = (const float*)d_in[20];

    k_fused<<<GRID_, NT_>>>(x, tokens, x_pe, conv_k, bn_g, bn_b, bn_rm, bn_rv,
                            fc_w1, fc_w2, ln1_g, ln1_b,
                            (const float4*)w_qkv,
                            (const float4*)w_out, (const float4*)b_out,
                            (const float4*)ln2_g, (const float4*)ln2_b,
                            (const float4*)ff_w1, (const float4*)ff_b1,
                            (const float4*)ff_w2, (const float4*)ff_b2,
                            (float4*)d_out);
}

// round 15
// speedup vs baseline: 1.8197x; 1.0782x over previous
#include <cuda_runtime.h>
#include <math.h>

#define D_     196
#define NCH_   64
#define H_     8
#define DH_    64
#define INNER_ 512
#define MLP_   784
#define SEQ_   65
#define NG_QKV 384   // 1536/4
#define NG_D   49    // 196/4
#define NG_MLP 196   // 784/4
#define GRID_  100
#define NT_    512

// ---- scratch (__device__ globals; no allocations allowed) ----
__device__ float  g_a[NCH_ * D_];
__device__ float4 g_xatt4[SEQ_ * NG_D];
__device__ float4 g_qkv4[SEQ_ * NG_QKV];    // q(pre-scaled)|k|v
__device__ unsigned g_cnt;                  // barrier arrival counter (self-resetting)
__device__ unsigned g_gen;                  // barrier generation (monotonic)

__device__ __forceinline__ void fma4(float4& a, float h, const float4& w) {
    a.x += h * w.x; a.y += h * w.y; a.z += h * w.z; a.w += h * w.w;
}
__device__ __forceinline__ void add4(float4& a, const float4& b) {
    a.x += b.x; a.y += b.y; a.z += b.z; a.w += b.w;
}
__device__ __forceinline__ float gelu_exact(float v) {
    return 0.5f * v * (1.f + erff(v * 0.70710678118654752f));
}

// grid-wide barrier: gridDim.x (100) <= #SMs (148), 1 block/SM -> all co-resident.
__device__ __forceinline__ void gsync() {
    __syncthreads();
    if (threadIdx.x == 0) {
        unsigned gen = *(volatile unsigned*)&g_gen;
        __threadfence();
        if (atomicAdd(&g_cnt, 1u) == gridDim.x - 1u) {
            atomicExch(&g_cnt, 0u);
            __threadfence();
            atomicAdd(&g_gen, 1u);
        } else {
            while (*(volatile unsigned*)&g_gen == gen) { __nanosleep(32); }
        }
        __threadfence();
    }
    __syncthreads();
}

__global__ __launch_bounds__(NT_, 1) void k_fused(
    const float* __restrict__ x, const float* __restrict__ tokens,
    const float* __restrict__ x_pe, const float* __restrict__ conv_k,
    const float* __restrict__ bn_g, const float* __restrict__ bn_b,
    const float* __restrict__ bn_rm, const float* __restrict__ bn_rv,
    const float* __restrict__ fc_w1, const float* __restrict__ fc_w2,
    const float* __restrict__ ln1_g, const float* __restrict__ ln1_b,
    const float4* __restrict__ wqkv4,
    const float4* __restrict__ wout4, const float4* __restrict__ bout4,
    const float4* __restrict__ ln2g4, const float4* __restrict__ ln2b4,
    const float4* __restrict__ ffw1_4, const float4* __restrict__ ffb1_4,
    const float4* __restrict__ ffw2_4, const float4* __restrict__ ffb2_4,
    float4* __restrict__ out4)
{
    __shared__ __align__(16) char sm[20160];
    const int tid = threadIdx.x;
    const int b   = blockIdx.x;

    // ================= PHASE A: LN1 + QKV (blocks 0..98) + gating (99) =================
    if (b < 99) {
        float*  hs   = (float*)sm;                 // 2*196 floats (ends 1568)
        float4* red  = (float4*)(sm + 1600);       // 3 slices * 128 gl * 2 rows (12288 B)
        float*  mrow = (float*)(sm + 13888);       // 2
        float*  rrow = (float*)(sm + 13896);       // 2

        const int tile  = b / 3;
        const int chunk = b - tile * 3;
        const int base  = tile * 2;                // rows base, base+1

        if (tid < 2 * D_) {
            int r = tid / D_, c = tid - r * D_;
            int row = base + r;
            hs[tid] = (row < SEQ_) ? x[row * D_ + c] : 0.f;
        }
        __syncthreads();

        const int warp = tid >> 5, lane = tid & 31;
        if (warp < 2) {
            float s1 = 0.f, s2 = 0.f;
            #pragma unroll
            for (int i = 0; i < 7; i++) {
                int c = lane + 32 * i;
                if (c < D_) { float v = hs[warp * D_ + c]; s1 += v; s2 += v * v; }
            }
            #pragma unroll
            for (int o = 16; o; o >>= 1) {
                s1 += __shfl_down_sync(0xffffffffu, s1, o);
                s2 += __shfl_down_sync(0xffffffffu, s2, o);
            }
            if (lane == 0) {
                float mean = s1 * (1.f / 196.f);
                float var  = s2 * (1.f / 196.f) - mean * mean;
                mrow[warp] = mean; rrow[warp] = rsqrtf(var + 1e-5f);
            }
        }
        __syncthreads();
        if (tid < 2 * D_) {
            int r = tid / D_, c = tid - r * D_;
            hs[tid] = (hs[tid] - mrow[r]) * rrow[r] * ln1_g[c] + ln1_b[c];
        }
        __syncthreads();

        const int gl = tid & 127;
        const int g  = chunk * 128 + gl;     // < 384
        const int s  = tid >> 7;             // K-slice 0..3, each 49
        float4 a0 = make_float4(0.f, 0.f, 0.f, 0.f);
        float4 a1 = make_float4(0.f, 0.f, 0.f, 0.f);

        const int kb = s * 49;
        const float4* W = wqkv4 + kb * NG_QKV + g;
        #pragma unroll 13
        for (int k = 0; k < 49; k++) {
            float4 w = W[k * NG_QKV];
            fma4(a0, hs[kb + k], w);
            fma4(a1, hs[D_ + kb + k], w);
        }
        if (s > 0) {
            red[((s - 1) * 128 + gl) * 2 + 0] = a0;
            red[((s - 1) * 128 + gl) * 2 + 1] = a1;
        }
        __syncthreads();
        if (s == 0) {
            float sc = (g < 128) ? 0.125f : 1.f;   // q pre-scale DH^-0.5
            #pragma unroll
            for (int ss = 0; ss < 3; ss++) {
                add4(a0, red[(ss * 128 + gl) * 2 + 0]);
                add4(a1, red[(ss * 128 + gl) * 2 + 1]);
            }
            a0.x *= sc; a0.y *= sc; a0.z *= sc; a0.w *= sc;
            a1.x *= sc; a1.y *= sc; a1.z *= sc; a1.w *= sc;
            if (base < SEQ_)     g_qkv4[base * NG_QKV + g]       = a0;
            if (base + 1 < SEQ_) g_qkv4[(base + 1) * NG_QKV + g] = a1;
        }
    } else {
        // ---------------- gating (block 99) ----------------
        float* b1s = (float*)sm;              // 64
        float* b2s = (float*)(sm + 256);      // 64
        float* hid = (float*)(sm + 512);      // 12
        float* cs  = (float*)(sm + 576);      // 64

        const int warp = tid >> 5, lane = tid & 31;
        const float k0 = conv_k[3], k1 = conv_k[4], k2 = conv_k[5];
        const float rm  = bn_rm[0];
        const float inv = rsqrtf(bn_rv[0] + 1e-5f) * bn_g[0];
        const float bb  = bn_b[0];

        for (int ch = warp; ch < NCH_; ch += 16) {
            const float* row = x_pe + ch * D_;
            float s = 0.f;
            for (int d = lane; d < D_; d += 32) {
                float xm = (d > 0)      ? row[d - 1] : 0.f;
                float xc = row[d];
                float xp = (d < D_ - 1) ? row[d + 1] : 0.f;
                float conv = k0 * xm + k1 * xc + k2 * xp;
                float bn = (conv - rm) * inv + bb;
                float av = fmaxf(bn, 0.f);
                g_a[ch * D_ + d] = av;
                s += av;
            }
            #pragma unroll
            for (int o = 16; o; o >>= 1) s += __shfl_down_sync(0xffffffffu, s, o);
            if (lane == 0) b1s[ch] = s * (1.f / 196.f);
        }
        __syncthreads();

        if (tid < NCH_) {
            const float bi = b1s[tid];
            float mx = -1e30f, mn = 1e30f;
            int cnt_nonpos = 0, rank = 0;
            #pragma unroll 8
            for (int j = 0; j < NCH_; j++) {
                float bj = b1s[j];
                mx = fmaxf(mx, bj); mn = fminf(mn, bj);
                if (bj <= 0.f) cnt_nonpos++;
                if (bj < bi || (bj == bi && j < tid)) rank++;
            }
            int middle = (mx < 0.f || mn > 0.f) ? 32 : (mx > 0.f ? cnt_nonpos : 0);
            float b2;
            if (rank < middle) {
                float ls = (float)middle;
                b2 = bi - 1.f / (1.f + powf(ls, bi));
            } else {
                float le = (float)(NCH_ - middle);
                b2 = bi + 1.f / (1.f + powf(le, -bi));
            }
            b2s[tid] = b2;
        }
        __syncthreads();
        if (tid < 12) {
            float s = 0.f;
            #pragma unroll 8
            for (int i = 0; i < NCH_; i++) s += b2s[i] * fc_w1[i * 12 + tid];
            hid[tid] = fmaxf(s, 0.f);
        }
        __syncthreads();
        if (tid < NCH_) {
            float s = 0.f;
            #pragma unroll
            for (int j = 0; j < 12; j++) s += hid[j] * fc_w2[j * NCH_ + tid];
            cs[tid] = 1.f / (1.f + expf(-s));
        }
        __syncthreads();
        float* xatt = (float*)g_xatt4;
        for (int idx = tid; idx < NCH_ * D_; idx += NT_)
            xatt[idx] = g_a[idx] * cs[idx / D_];
        for (int d = tid; d < D_; d += NT_)
            xatt[NCH_ * D_ + d] = tokens[d];
    }
    gsync();   // the ONLY grid barrier

    // ================= PHASE B: per-row pipeline (blocks 0..64) =================
    if (b >= SEQ_) return;
    const int n = b;
    const float* qkv = (const float*)g_qkv4;

    float*  qs    = (float*)sm;                // 512 f          [0,2048)
    float*  scs   = (float*)(sm + 2048);       // 8*66 f         [2048,4160)
    float*  smaxp = (float*)(sm + 4160);       // 8
    float*  sinvp = (float*)(sm + 4192);       // 8
    float*  os    = (float*)(sm + 4224);       // 512 f          [4224,6272)
    float4* red   = (float4*)(sm + 6272);      // 7*49 f4        [6272,11760)
    float4* x2s   = (float4*)(sm + 11760);     // 49 f4          [11760,12544)
    float4* h2s   = (float4*)(sm + 12544);     // 49 f4          [12544,13328)
    float*  p1    = (float*)(sm + 13328);      // 49
    float*  p2    = (float*)(sm + 13524);      // 49
    float*  stats = (float*)(sm + 13720);      // 2
    float4* ts4   = (float4*)(sm + 13744);     // 196 f4         [13744,16880)
    float4* red1  = (float4*)(sm + 16880);     // 196 f4         [16880,20016)

    // ---- attention: head h = tid>>6, lane-within-head d = tid&63 ----
    const int h = tid >> 6, d = tid & 63;
    qs[tid] = qkv[n * 1536 + tid];            // q row (pre-scaled)
    __syncthreads();

    const float* qh = qs + h * DH_;
    {
        const float4* kr = (const float4*)(qkv + d * 1536 + INNER_ + h * DH_);
        float s = 0.f;
        #pragma unroll
        for (int i = 0; i < 16; i++) {
            float4 k4 = kr[i];
            s += qh[4*i] * k4.x + qh[4*i+1] * k4.y + qh[4*i+2] * k4.z + qh[4*i+3] * k4.w;
        }
        scs[h * 66 + d] = s;
        if (d == 0) {
            const float4* kr2 = (const float4*)(qkv + 64 * 1536 + INNER_ + h * DH_);
            float s2 = 0.f;
            #pragma unroll
            for (int i = 0; i < 16; i++) {
                float4 k4 = kr2[i];
                s2 += qh[4*i] * k4.x + qh[4*i+1] * k4.y + qh[4*i+2] * k4.z + qh[4*i+3] * k4.w;
            }
            scs[h * 66 + 64] = s2;
        }
    }
    __syncthreads();
    if (d < 32) {
        float m = fmaxf(scs[h * 66 + d], scs[h * 66 + d + 32]);
        if (d == 0) m = fmaxf(m, scs[h * 66 + 64]);
        #pragma unroll
        for (int o = 16; o; o >>= 1) m = fmaxf(m, __shfl_down_sync(0xffffffffu, m, o));
        if (d == 0) smaxp[h] = m;
    }
    __syncthreads();
    {
        float mx = smaxp[h];
        scs[h * 66 + d] = expf(scs[h * 66 + d] - mx);
        if (d == 0) scs[h * 66 + 64] = expf(scs[h * 66 + 64] - mx);
    }
    __syncthreads();
    if (d < 32) {
        float s = scs[h * 66 + d] + scs[h * 66 + d + 32];
        if (d == 0) s += scs[h * 66 + 64];
        #pragma unroll
        for (int o = 16; o; o >>= 1) s += __shfl_down_sync(0xffffffffu, s, o);
        if (d == 0) sinvp[h] = 1.f / s;
    }
    __syncthreads();
    {
        const float* vb = qkv + 2 * INNER_ + h * DH_ + d;
        const float* p  = scs + h * 66;
        float acc = 0.f;
        #pragma unroll 16
        for (int m = 0; m < SEQ_; m++) acc += p[m] * vb[m * 1536];
        os[tid] = acc * sinvp[h];
    }
    __syncthreads();

    // ---- out-proj (K=512, 8 slices of 64) + residuals + LN2 ----
    const int s8 = tid / NG_D;                 // 0..10 (use <8)
    const int g  = tid - s8 * NG_D;            // <49
    float4 vacc = make_float4(0.f, 0.f, 0.f, 0.f);
    if (s8 < 8) {
        const int kb = s8 * 64;
        const float4* W = wout4 + kb * NG_D + g;
        const float* hb = os + kb;
        #pragma unroll 16
        for (int k = 0; k < 64; k++) fma4(vacc, hb[k], W[k * NG_D]);
        if (s8 > 0) red[(s8 - 1) * NG_D + g] = vacc;
    }
    __syncthreads();
    if (s8 == 0) {
        #pragma unroll
        for (int ss = 0; ss < 7; ss++) add4(vacc, red[ss * NG_D + g]);
        float4 bo = bout4[g];
        float4 xv = ((const float4*)x)[n * NG_D + g];
        float4 xa = g_xatt4[n * NG_D + g];
        vacc.x += bo.x + xv.x + xa.x;
        vacc.y += bo.y + xv.y + xa.y;
        vacc.z += bo.z + xv.z + xa.z;
        vacc.w += bo.w + xv.w + xa.w;
        x2s[g] = vacc;
        p1[g] = vacc.x + vacc.y + vacc.z + vacc.w;
        p2[g] = vacc.x*vacc.x + vacc.y*vacc.y + vacc.z*vacc.z + vacc.w*vacc.w;
    }
    __syncthreads();
    if (tid < 32) {
        float t1 = 0.f, t2 = 0.f;
        for (int i = tid; i < NG_D; i += 32) { t1 += p1[i]; t2 += p2[i]; }
        #pragma unroll
        for (int o = 16; o; o >>= 1) {
            t1 += __shfl_down_sync(0xffffffffu, t1, o);
            t2 += __shfl_down_sync(0xffffffffu, t2, o);
        }
        if (tid == 0) {
            float mean = t1 * (1.f / 196.f);
            float var  = t2 * (1.f / 196.f) - mean * mean;
            stats[0] = mean; stats[1] = rsqrtf(var + 1e-5f);
        }
    }
    __syncthreads();
    if (s8 == 0) {
        float m = stats[0], rs = stats[1];
        float4 v = x2s[g], gg = ln2g4[g], bb = ln2b4[g], hh;
        hh.x = (v.x - m) * rs * gg.x + bb.x;
        hh.y = (v.y - m) * rs * gg.y + bb.y;
        hh.z = (v.z - m) * rs * gg.z + bb.z;
        hh.w = (v.w - m) * rs * gg.w + bb.w;
        h2s[g] = hh;
    }
    __syncthreads();

    // ---- FF1 (K=196, 2 slices of 98) + GELU ----
    float4 facc = make_float4(0.f, 0.f, 0.f, 0.f);
    if (tid < 392) {
        const int s1 = tid / NG_MLP;           // 0..1
        const int gg = tid - s1 * NG_MLP;      // <196
        const float* hh = (const float*)h2s;   // 196 floats
        const int kb = s1 * 98;
        const float4* W = ffw1_4 + kb * NG_MLP + gg;
        #pragma unroll 14
        for (int k = 0; k < 98; k++) fma4(facc, hh[kb + k], W[k * NG_MLP]);
        if (s1 == 1) red1[gg] = facc;
    }
    __syncthreads();
    if (tid < NG_MLP) {
        add4(facc, red1[tid]);
        float4 fb = ffb1_4[tid], t;
        t.x = gelu_exact(facc.x + fb.x);
        t.y = gelu_exact(facc.y + fb.y);
        t.z = gelu_exact(facc.z + fb.z);
        t.w = gelu_exact(facc.w + fb.w);
        ts4[tid] = t;
    }
    __syncthreads();

    // ---- FF2 (K=784, 8 slices of 98) + residual -> out ----
    float4 oacc = make_float4(0.f, 0.f, 0.f, 0.f);
    if (s8 < 8) {
        const int kb = s8 * 98;
        const float* tf = (const float*)ts4;   // 784 floats
        const float4* W = ffw2_4 + kb * NG_D + g;
        #pragma unroll 14
        for (int k = 0; k < 98; k++) fma4(oacc, tf[kb + k], W[k * NG_D]);
        if (s8 > 0) red[(s8 - 1) * NG_D + g] = oacc;
    }
    __syncthreads();
    if (s8 == 0) {
        #pragma unroll
        for (int ss = 0; ss < 7; ss++) add4(oacc, red[ss * NG_D + g]);
        float4 fb = ffb2_4[g], x2 = x2s[g];
        oacc.x += fb.x + x2.x; oacc.y += fb.y + x2.y;
        oacc.z += fb.z + x2.z; oacc.w += fb.w + x2.w;
        out4[n * NG_D + g] = oacc;
    }
}

// ============================================================
extern "C" void kernel_launch(void* const* d_in, const int* in_sizes, int n_in,
                              void* d_out, int out_size)
{
    const float* x      = (const float*)d_in[0];
    const float* tokens = (const float*)d_in[1];
    const float* x_pe   = (const float*)d_in[2];
    const float* conv_k = (const float*)d_in[3];
    const float* bn_g   = (const float*)d_in[4];
    const float* bn_b   = (const float*)d_in[5];
    const float* bn_rm  = (const float*)d_in[6];
    const float* bn_rv  = (const float*)d_in[7];
    const float* fc_w1  = (const float*)d_in[8];
    const float* fc_w2  = (const float*)d_in[9];
    const float* ln1_g  = (const float*)d_in[10];
    const float* ln1_b  = (const float*)d_in[11];
    const float* ln2_g  = (const float*)d_in[12];
    const float* ln2_b  = (const float*)d_in[13];
    const float* w_qkv  = (const float*)d_in[14];
    const float* w_out  = (const float*)d_in[15];
    const float* b_out  = (const float*)d_in[16];
    const float* ff_w1  = (const float*)d_in[17];
    const float* ff_b1  = (const float*)d_in[18];
    const float* ff_w2  = (const float*)d_in[19];
    const float* ff_b2  = (const float*)d_in[20];

    k_fused<<<GRID_, NT_>>>(x, tokens, x_pe, conv_k, bn_g, bn_b, bn_rm, bn_rv,
                            fc_w1, fc_w2, ln1_g, ln1_b,
                            (const float4*)w_qkv,
                            (const float4*)w_out, (const float4*)b_out,
                            (const float4*)ln2_g, (const float4*)ln2_b,
                            (const float4*)ff_w1, (const float4*)ff_b1,
                            (const float4*)ff_w2, (const float4*)ff_b2,
                            (float4*)d_out);
}